// round 9
// baseline (speedup 1.0000x reference)
#include <cuda_runtime.h>
#include <cuda_fp16.h>
#include <cstdint>

// ---------------------------------------------------------------------------
// B=8, L=2048, D=1024, FF_MULT=2;  M = 16384
// ---------------------------------------------------------------------------
#define MROWS 16384
#define EPS_LN 1e-6f

// ---------------------------------------------------------------------------
// Scratch (device globals)
// ---------------------------------------------------------------------------
__device__ __half g_norm  [MROWS * 1024];
__device__ __half g_H12   [MROWS * 2048];
__device__ float  g_x1    [MROWS * 1024];
__device__ __half g_ffnorm[MROWS * 1024];
__device__ __half g_H3    [MROWS * 2048];
__device__ __half g_w1T   [2048 * 1024];   // [ssm_w1|bwd_w1]^T  (N=2048, K=1024) K-major
__device__ __half g_w2T   [1024 * 2048];   // [ssm_w2;bwd_w2]^T  (N=1024, K=2048)
__device__ __half g_ffw1T [2048 * 1024];   // ff_w1^T
__device__ __half g_ffw2T [1024 * 2048];   // ff_w2^T
__device__ float  g_emb   [8 * 3072];
__device__ float  g_ffada [8 * 3072];

// ---------------------------------------------------------------------------
// Helpers
// ---------------------------------------------------------------------------
__device__ __forceinline__ uint32_t smem_u32(const void* p) {
    return (uint32_t)__cvta_generic_to_shared(p);
}
__device__ __forceinline__ float gelu_erf_f(float x) {
    return 0.5f * x * (1.f + erff(x * 0.70710678118654752f));
}
__device__ __forceinline__ float gelu_tanh_f(float x) {
    float x3 = x * x * x;
    return 0.5f * x * (1.f + tanhf(0.79788456080286536f * (x + 0.044715f * x3)));
}
#define SWZ(off) ((off) ^ (((off) >> 3) & 0x70))

#define CP_ASYNC16(dst, src) \
    asm volatile("cp.async.cg.shared.global [%0], [%1], 16;" :: "r"(dst), "l"(src) : "memory")

// ---------------------------------------------------------------------------
// transpose + fp32->fp16:  dst[(n+rowOff)*dstStride + colOff + k] = src[k*N + n]
// ---------------------------------------------------------------------------
__global__ void transpose_convert(__half* __restrict__ dst, const float* __restrict__ src,
                                  int N, int dstStride, int rowOff, int colOff)
{
    __shared__ float tile[32][33];
    int k0 = blockIdx.y * 32, n0 = blockIdx.x * 32;
    int tx = threadIdx.x, ty = threadIdx.y;
    #pragma unroll
    for (int j = 0; j < 4; j++)
        tile[ty + j * 8][tx] = src[(size_t)(k0 + ty + j * 8) * N + n0 + tx];
    __syncthreads();
    #pragma unroll
    for (int j = 0; j < 4; j++) {
        int n = n0 + ty + j * 8, k = k0 + tx;
        dst[(size_t)(n + rowOff) * dstStride + colOff + k] = __float2half(tile[tx][ty + j * 8]);
    }
}

// ---------------------------------------------------------------------------
// adaLN
// ---------------------------------------------------------------------------
__global__ __launch_bounds__(256)
void adaln_kernel(const float* __restrict__ t,
                  const float* __restrict__ ada_w,  const float* __restrict__ ada_b,
                  const float* __restrict__ ffada_w,const float* __restrict__ ffada_b,
                  float* __restrict__ emb, float* __restrict__ ffada)
{
    __shared__ float st[8][1024];
    int tid = threadIdx.x;
    for (int i = tid; i < 8 * 1024; i += 256) {
        float v = t[i];
        st[i >> 10][i & 1023] = v / (1.f + expf(-v));
    }
    __syncthreads();

    int col = blockIdx.x * 256 + tid;
    const float* W; const float* Bv; float* O; int c;
    if (col < 3072) { W = ada_w;   Bv = ada_b;   O = emb;   c = col; }
    else            { W = ffada_w; Bv = ffada_b; O = ffada; c = col - 3072; }

    float acc[8];
    #pragma unroll
    for (int b = 0; b < 8; b++) acc[b] = 0.f;
    #pragma unroll 4
    for (int k = 0; k < 1024; k++) {
        float wv = W[(size_t)k * 3072 + c];
        #pragma unroll
        for (int b = 0; b < 8; b++) acc[b] += st[b][k] * wv;
    }
    float bv = Bv[c];
    #pragma unroll
    for (int b = 0; b < 8; b++) O[b * 3072 + c] = acc[b] + bv;
}

// ---------------------------------------------------------------------------
// LN + adaLN modulation (mask is int32)
// ---------------------------------------------------------------------------
template<bool MASKED>
__global__ __launch_bounds__(256)
void ln_mod_kernel(const float* __restrict__ x, const float* __restrict__ ada,
                   const int* __restrict__ maskp, __half* __restrict__ out)
{
    int row = blockIdx.x;
    int tid = threadIdx.x;
    const float* xr = x + (size_t)row * 1024;
    float4 xv = ((const float4*)xr)[tid];
    float s = xv.x + xv.y + xv.z + xv.w;
    float q = xv.x * xv.x + xv.y * xv.y + xv.z * xv.z + xv.w * xv.w;
    #pragma unroll
    for (int o = 16; o; o >>= 1) {
        s += __shfl_xor_sync(0xffffffffu, s, o);
        q += __shfl_xor_sync(0xffffffffu, q, o);
    }
    __shared__ float ss[8], sq[8];
    __shared__ float mu_s, rs_s;
    int w = tid >> 5;
    if ((tid & 31) == 0) { ss[w] = s; sq[w] = q; }
    __syncthreads();
    if (tid == 0) {
        float S = 0.f, Q = 0.f;
        #pragma unroll
        for (int i = 0; i < 8; i++) { S += ss[i]; Q += sq[i]; }
        float mu = S * (1.f / 1024.f);
        float var = Q * (1.f / 1024.f) - mu * mu;
        mu_s = mu; rs_s = rsqrtf(var + EPS_LN);
    }
    __syncthreads();

    __half* orow = out + (size_t)row * 1024;
    if (MASKED && maskp[row] == 0) {
        ((uint2*)orow)[tid] = make_uint2(0u, 0u);
        return;
    }
    float mu = mu_s, rs = rs_s;
    int b = row >> 11;
    const float* shp = ada + b * 3072;
    int c = tid * 4;
    float4 sh4 = *(const float4*)(shp + c);
    float4 sc4 = *(const float4*)(shp + 1024 + c);
    float o0 = (xv.x - mu) * rs * (1.f + sc4.x) + sh4.x;
    float o1 = (xv.y - mu) * rs * (1.f + sc4.y) + sh4.y;
    float o2 = (xv.z - mu) * rs * (1.f + sc4.z) + sh4.z;
    float o3 = (xv.w - mu) * rs * (1.f + sc4.w) + sh4.w;
    *(__half2*)(orow + c)     = __floats2half2_rn(o0, o1);
    *(__half2*)(orow + c + 2) = __floats2half2_rn(o2, o3);
}

// ---------------------------------------------------------------------------
// fp16 mma.sync GEMM, cp.async 3-stage, CTA tile 128x128, BK=64.
// 4 warps, warp tile 64x64, REGISTER DOUBLE-BUFFERED fragments:
// ldmatrix for k-step kk+16 issued before MMAs of kk -> LDSM latency exposed
// once per 64-K stage instead of 4x.
// EPI: 0 gelu_erf(+split bias)->half | 1 mask,+b0+b1,gate,+resid->float
//      2 gelu_tanh(+b0)->half       | 3 +b0,gate,+resid->float
// ---------------------------------------------------------------------------
#define GSM_TOTAL 98304

__device__ __forceinline__ void issue_stage64(
    uint32_t sbase, const __half* __restrict__ A, const __half* __restrict__ Bw,
    int row0, int col0, int K, int buf, int chunk, int tid)
{
    int k0 = chunk * 64;
    uint32_t a_s = sbase + (uint32_t)buf * 16384u;
    uint32_t b_s = sbase + 49152u + (uint32_t)buf * 16384u;
    #pragma unroll
    for (int j = 0; j < 8; j++) {
        int lin = tid + j * 128;
        int r = lin >> 3, g = lin & 7;
        uint32_t off = (uint32_t)(r * 128 + g * 16);
        CP_ASYNC16(a_s + SWZ(off), A + (size_t)(row0 + r) * K + k0 + g * 8);
    }
    #pragma unroll
    for (int j = 0; j < 8; j++) {
        int lin = tid + j * 128;
        int r = lin >> 3, g = lin & 7;
        uint32_t off = (uint32_t)(r * 128 + g * 16);
        CP_ASYNC16(b_s + SWZ(off), Bw + (size_t)(col0 + r) * K + k0 + g * 8);
    }
    asm volatile("cp.async.commit_group;" ::: "memory");
}

__device__ __forceinline__ void load_frags(
    uint32_t a_sm, uint32_t b_sm, int a_r, int a_c, int b_r, int b_c, int kk,
    uint32_t aF[4][4], uint32_t bF[8][2])
{
    #pragma unroll
    for (int mi = 0; mi < 4; mi++) {
        uint32_t off = (uint32_t)((a_r + mi * 16) * 128 + (kk + a_c) * 2);
        uint32_t addr = a_sm + SWZ(off);
        asm volatile("ldmatrix.sync.aligned.m8n8.x4.shared.b16 {%0,%1,%2,%3}, [%4];"
            : "=r"(aF[mi][0]), "=r"(aF[mi][1]), "=r"(aF[mi][2]), "=r"(aF[mi][3])
            : "r"(addr));
    }
    #pragma unroll
    for (int nt = 0; nt < 4; nt++) {
        uint32_t off = (uint32_t)((b_r + nt * 16) * 128 + (kk + b_c) * 2);
        uint32_t addr = b_sm + SWZ(off);
        asm volatile("ldmatrix.sync.aligned.m8n8.x4.shared.b16 {%0,%1,%2,%3}, [%4];"
            : "=r"(bF[2*nt][0]), "=r"(bF[2*nt][1]), "=r"(bF[2*nt+1][0]), "=r"(bF[2*nt+1][1])
            : "r"(addr));
    }
}

__device__ __forceinline__ void do_mma(
    uint32_t aF[4][4], uint32_t bF[8][2], float acc[4][8][4])
{
    #pragma unroll
    for (int mi = 0; mi < 4; mi++)
        #pragma unroll
        for (int j = 0; j < 8; j++)
            asm volatile(
                "mma.sync.aligned.m16n8k16.row.col.f32.f16.f16.f32 "
                "{%0,%1,%2,%3}, {%4,%5,%6,%7}, {%8,%9}, {%0,%1,%2,%3};"
                : "+f"(acc[mi][j][0]), "+f"(acc[mi][j][1]),
                  "+f"(acc[mi][j][2]), "+f"(acc[mi][j][3])
                : "r"(aF[mi][0]), "r"(aF[mi][1]), "r"(aF[mi][2]), "r"(aF[mi][3]),
                  "r"(bF[j][0]), "r"(bF[j][1]));
}

template<int EPI>
__global__ __launch_bounds__(128, 2)
void gemm_f16(const __half* __restrict__ A, const __half* __restrict__ Bw,
              int N, int K,
              const float* __restrict__ bias0, const float* __restrict__ bias1, int bsplit,
              const float* __restrict__ resid, const float* __restrict__ ada,
              const int* __restrict__ maskp,
              void* __restrict__ outp)
{
    extern __shared__ char smem[];
    uint32_t sbase = smem_u32(smem);
    const int tid  = threadIdx.x;
    const int lane = tid & 31;
    const int warp = tid >> 5;
    const int wm = warp & 1;
    const int wn = warp >> 1;
    const int row0 = blockIdx.y * 128;
    const int col0 = blockIdx.x * 128;
    const int nk = K >> 6;

    float acc[4][8][4];
    #pragma unroll
    for (int i = 0; i < 4; i++)
        #pragma unroll
        for (int j = 0; j < 8; j++)
            #pragma unroll
            for (int v = 0; v < 4; v++) acc[i][j][v] = 0.f;

    issue_stage64(sbase, A, Bw, row0, col0, K, 0, 0, tid);
    issue_stage64(sbase, A, Bw, row0, col0, K, 1, 1, tid);

    const int a_r = wm * 64 + (lane & 15);
    const int a_c = (lane >> 4) * 8;
    const int b_r = wn * 64 + (lane & 7) + ((lane >> 4) << 3);
    const int b_c = ((lane >> 3) & 1) * 8;

    uint32_t aF[2][4][4];
    uint32_t bF[2][8][2];

    for (int i = 0; i < nk; i++) {
        int s = i % 3;
        asm volatile("cp.async.wait_group 1;" ::: "memory");
        __syncthreads();
        if (i + 2 < nk) issue_stage64(sbase, A, Bw, row0, col0, K, (i + 2) % 3, i + 2, tid);
        else asm volatile("cp.async.commit_group;" ::: "memory");

        uint32_t a_sm = sbase + (uint32_t)s * 16384u;
        uint32_t b_sm = sbase + 49152u + (uint32_t)s * 16384u;

        load_frags(a_sm, b_sm, a_r, a_c, b_r, b_c, 0, aF[0], bF[0]);
        #pragma unroll
        for (int kx = 0; kx < 4; kx++) {
            int cur = kx & 1;
            if (kx < 3)
                load_frags(a_sm, b_sm, a_r, a_c, b_r, b_c, (kx + 1) * 16,
                           aF[cur ^ 1], bF[cur ^ 1]);
            do_mma(aF[cur], bF[cur], acc);
        }
        __syncthreads();
    }

    // ---------------- epilogue ----------------
    const int lr = lane >> 2;
    const int lc = (lane & 3) * 2;
    #pragma unroll
    for (int i = 0; i < 4; i++) {
        #pragma unroll
        for (int j = 0; j < 8; j++) {
            int col = col0 + wn * 64 + j * 8 + lc;
            #pragma unroll
            for (int h = 0; h < 2; h++) {
                int r = row0 + wm * 64 + i * 16 + lr + h * 8;
                float v0 = acc[i][j][h * 2 + 0];
                float v1 = acc[i][j][h * 2 + 1];
                if (EPI == 0 || EPI == 2) {
                    float b0 = (col     < bsplit) ? bias0[col]     : bias1[col - bsplit];
                    float b1 = (col + 1 < bsplit) ? bias0[col + 1] : bias1[col + 1 - bsplit];
                    v0 += b0; v1 += b1;
                    if (EPI == 0) { v0 = gelu_erf_f(v0);  v1 = gelu_erf_f(v1); }
                    else          { v0 = gelu_tanh_f(v0); v1 = gelu_tanh_f(v1); }
                    __half* o = (__half*)outp + (size_t)r * N + col;
                    *(__half2*)o = __floats2half2_rn(v0, v1);
                } else {
                    int bi = r >> 11;
                    float g0 = ada[bi * 3072 + 2048 + col];
                    float g1 = ada[bi * 3072 + 2048 + col + 1];
                    if (EPI == 1) {
                        v0 += bias0[col]     + bias1[col];
                        v1 += bias0[col + 1] + bias1[col + 1];
                        if (maskp[r] == 0) { v0 = 0.f; v1 = 0.f; }
                    } else {
                        v0 += bias0[col];
                        v1 += bias0[col + 1];
                    }
                    const float* rp = resid + (size_t)r * N + col;
                    float2 res;
                    res.x = rp[0] + g0 * v0;
                    res.y = rp[1] + g1 * v1;
                    *(float2*)((float*)outp + (size_t)r * N + col) = res;
                }
            }
        }
    }
}

// ---------------------------------------------------------------------------
// launch — ordered so ncu (-s 5 -c 1) captures GEMM1 at launch index 5
// ---------------------------------------------------------------------------
extern "C" void kernel_launch(void* const* d_in, const int* in_sizes, int n_in,
                              void* d_out, int out_size)
{
    const float* x       = (const float*)d_in[0];
    const float* t       = (const float*)d_in[1];
    const int*   mask    = (const int*)d_in[2];
    const float* ada_w   = (const float*)d_in[3];
    const float* ada_b   = (const float*)d_in[4];
    const float* ssm_w1  = (const float*)d_in[5];
    const float* ssm_b1  = (const float*)d_in[6];
    const float* ssm_w2  = (const float*)d_in[7];
    const float* ssm_b2  = (const float*)d_in[8];
    const float* bwd_w1  = (const float*)d_in[9];
    const float* bwd_b1  = (const float*)d_in[10];
    const float* bwd_w2  = (const float*)d_in[11];
    const float* bwd_b2  = (const float*)d_in[12];
    const float* ffada_w = (const float*)d_in[13];
    const float* ffada_b = (const float*)d_in[14];
    const float* ff_w1   = (const float*)d_in[15];
    const float* ff_b1   = (const float*)d_in[16];
    const float* ff_w2   = (const float*)d_in[17];
    const float* ff_b2   = (const float*)d_in[18];
    float* out = (float*)d_out;

    __half *norm_p, *h12_p, *ffnorm_p, *h3_p, *w1T_p, *w2T_p, *fw1T_p, *fw2T_p;
    float  *x1_p, *emb_p, *ffada_p;
    cudaGetSymbolAddress((void**)&norm_p,   g_norm);
    cudaGetSymbolAddress((void**)&h12_p,    g_H12);
    cudaGetSymbolAddress((void**)&x1_p,     g_x1);
    cudaGetSymbolAddress((void**)&ffnorm_p, g_ffnorm);
    cudaGetSymbolAddress((void**)&h3_p,     g_H3);
    cudaGetSymbolAddress((void**)&w1T_p,    g_w1T);
    cudaGetSymbolAddress((void**)&w2T_p,    g_w2T);
    cudaGetSymbolAddress((void**)&fw1T_p,   g_ffw1T);
    cudaGetSymbolAddress((void**)&fw2T_p,   g_ffw2T);
    cudaGetSymbolAddress((void**)&emb_p,    g_emb);
    cudaGetSymbolAddress((void**)&ffada_p,  g_ffada);

    cudaFuncSetAttribute(gemm_f16<0>, cudaFuncAttributeMaxDynamicSharedMemorySize, GSM_TOTAL);
    cudaFuncSetAttribute(gemm_f16<1>, cudaFuncAttributeMaxDynamicSharedMemorySize, GSM_TOTAL);
    cudaFuncSetAttribute(gemm_f16<2>, cudaFuncAttributeMaxDynamicSharedMemorySize, GSM_TOTAL);
    cudaFuncSetAttribute(gemm_f16<3>, cudaFuncAttributeMaxDynamicSharedMemorySize, GSM_TOTAL);

    dim3 tb(32, 8);

    // [0] adaLN vectors (no deps)
    adaln_kernel<<<24, 256>>>(t, ada_w, ada_b, ffada_w, ffada_b, emb_p, ffada_p);
    // [1] LN1 (needs emb)
    ln_mod_kernel<true><<<MROWS, 256>>>(x, emb_p, mask, norm_p);
    // [2][3] w1T converts (GEMM1 weights)
    transpose_convert<<<dim3(32, 32), tb>>>(w1T_p,  ssm_w1, 1024, 1024, 0,    0);
    transpose_convert<<<dim3(32, 32), tb>>>(w1T_p,  bwd_w1, 1024, 1024, 1024, 0);
    // [4] first half of w2T (filler before profiled slot)
    transpose_convert<<<dim3(32, 32), tb>>>(w2T_p,  ssm_w2, 1024, 2048, 0,    0);

    // [5] GEMM1 — profiled by ncu (-s 5 -c 1)
    gemm_f16<0><<<dim3(16, 128), 128, GSM_TOTAL>>>(norm_p, w1T_p, 2048, 1024,
                                                   ssm_b1, bwd_b1, 1024,
                                                   nullptr, nullptr, nullptr, h12_p);

    // [6..8] remaining converts
    transpose_convert<<<dim3(32, 32), tb>>>(w2T_p,  bwd_w2, 1024, 2048, 0,    1024);
    transpose_convert<<<dim3(64, 32), tb>>>(fw1T_p, ff_w1,  2048, 1024, 0,    0);
    transpose_convert<<<dim3(32, 64), tb>>>(fw2T_p, ff_w2,  1024, 2048, 0,    0);

    // [9] GEMM2: x1 = x + gate_msa * mask * (H12 @ [w2;w2b] + b2a + b2b)
    gemm_f16<1><<<dim3(8, 128), 128, GSM_TOTAL>>>(h12_p, w2T_p, 1024, 2048,
                                                  ssm_b2, bwd_b2, 0,
                                                  x, emb_p, mask, x1_p);

    // [10] LN2
    ln_mod_kernel<false><<<MROWS, 256>>>(x1_p, ffada_p, nullptr, ffnorm_p);

    // [11] GEMM3: H3 = gelu_tanh(ffnorm @ ff_w1 + b1)
    gemm_f16<2><<<dim3(16, 128), 128, GSM_TOTAL>>>(ffnorm_p, fw1T_p, 2048, 1024,
                                                   ff_b1, ff_b1, 1 << 30,
                                                   nullptr, nullptr, nullptr, h3_p);

    // [12] GEMM4: out = x1 + gate_mlp * (H3 @ ff_w2 + b2)
    gemm_f16<3><<<dim3(8, 128), 128, GSM_TOTAL>>>(h3_p, fw2T_p, 1024, 2048,
                                                  ff_b2, ff_b2, 1 << 30,
                                                  x1_p, ffada_p, nullptr, out);
}